// round 10
// baseline (speedup 1.0000x reference)
#include <cuda_runtime.h>
#include <cuda_bf16.h>

// out[b,t,c] = (x[b,src,c] + noise[b,src,c]*0.1f) * scale[b]
// src = (t - (shifts[b] - MAX_SHIFT)) mod T
// B=64, T=4096, C=128, fp32.
// Sustained-mode winner family: float4 + .cs streaming hints + hoisted scale.
// This round: 128-thread blocks (finer wave granularity probe).

#define B_DIM 64
#define T_DIM 4096
#define C_DIM 128
#define MAX_SHIFT 409
#define NOISE_STD 0.1f

#define C4 (C_DIM / 4)   // 32 float4 per (b,t) row
#define THREADS 128

__global__ __launch_bounds__(THREADS)
void ts_augment_kernel(const float4* __restrict__ x,
                       const float4* __restrict__ noise,
                       const float*  __restrict__ scale,
                       const int*    __restrict__ shifts,
                       float4*       __restrict__ out)
{
    // flat index over B * T * C4 = 8,388,608; grid*block covers exactly.
    unsigned idx = blockIdx.x * blockDim.x + threadIdx.x;
    unsigned c4 = idx & (C4 - 1);            // idx % 32
    unsigned t  = (idx >> 5) & (T_DIM - 1);  // (idx / 32) % 4096
    unsigned b  = idx >> 17;                 // idx / (32*4096)

    int s = shifts[b] - MAX_SHIFT;           // [-409, 409]
    int src = (int)t - s;                    // [-409, 4504]
    if (src < 0)           src += T_DIM;
    else if (src >= T_DIM) src -= T_DIM;

    unsigned src_idx = (b << 17) + ((unsigned)src << 5) + c4;

    // Touch-once streams: evict-first reads, streaming store.
    float4 xv = __ldcs(&x[src_idx]);
    float4 nv = __ldcs(&noise[src_idx]);

    float sc  = __ldg(&scale[b]);
    float nsc = sc * NOISE_STD;   // out = x*sc + n*(0.1*sc): independent MUL + FMA per lane

    float4 o;
    o.x = fmaf(nv.x, nsc, xv.x * sc);
    o.y = fmaf(nv.y, nsc, xv.y * sc);
    o.z = fmaf(nv.z, nsc, xv.z * sc);
    o.w = fmaf(nv.w, nsc, xv.w * sc);

    __stcs(&out[idx], o);
}

extern "C" void kernel_launch(void* const* d_in, const int* in_sizes, int n_in,
                              void* d_out, int out_size)
{
    const float4* x      = (const float4*)d_in[0];
    const float4* noise  = (const float4*)d_in[1];
    const float*  scale  = (const float*)d_in[2];
    const int*    shifts = (const int*)d_in[3];
    float4* out = (float4*)d_out;

    const unsigned total = B_DIM * T_DIM * C4;   // 8,388,608
    const unsigned blocks = total / THREADS;     // 65536

    ts_augment_kernel<<<blocks, THREADS>>>(x, noise, scale, shifts, out);
}

// round 11
// speedup vs baseline: 1.0181x; 1.0181x over previous
#include <cuda_runtime.h>
#include <cuda_bf16.h>

// out[b,t,c] = (x[b,src,c] + noise[b,src,c]*0.1f) * scale[b]
// src = (t - (shifts[b] - MAX_SHIFT)) mod T
// B=64, T=4096, C=128, fp32.
// FINAL committed config (reproduced R3/R9; block-size curve 128/256/512 ->
// 61.09/59.87/61.50 us): float4 + .cs streaming hints + 256-thread blocks
// + hoisted scale. ~6.4 TB/s sustained on an irreducible 384 MB 2R:1W stream.

#define B_DIM 64
#define T_DIM 4096
#define C_DIM 128
#define MAX_SHIFT 409
#define NOISE_STD 0.1f

#define C4 (C_DIM / 4)   // 32 float4 per (b,t) row
#define THREADS 256

__global__ __launch_bounds__(THREADS)
void ts_augment_kernel(const float4* __restrict__ x,
                       const float4* __restrict__ noise,
                       const float*  __restrict__ scale,
                       const int*    __restrict__ shifts,
                       float4*       __restrict__ out)
{
    // flat index over B * T * C4 = 8,388,608; grid*block covers exactly.
    unsigned idx = blockIdx.x * blockDim.x + threadIdx.x;
    unsigned c4 = idx & (C4 - 1);            // idx % 32
    unsigned t  = (idx >> 5) & (T_DIM - 1);  // (idx / 32) % 4096
    unsigned b  = idx >> 17;                 // idx / (32*4096)

    int s = shifts[b] - MAX_SHIFT;           // [-409, 409]
    int src = (int)t - s;                    // [-409, 4504]
    if (src < 0)           src += T_DIM;
    else if (src >= T_DIM) src -= T_DIM;

    unsigned src_idx = (b << 17) + ((unsigned)src << 5) + c4;

    // Touch-once streams: evict-first reads, streaming store.
    float4 xv = __ldcs(&x[src_idx]);
    float4 nv = __ldcs(&noise[src_idx]);

    float sc  = __ldg(&scale[b]);
    float nsc = sc * NOISE_STD;   // out = x*sc + n*(0.1*sc): independent MUL + FMA per lane

    float4 o;
    o.x = fmaf(nv.x, nsc, xv.x * sc);
    o.y = fmaf(nv.y, nsc, xv.y * sc);
    o.z = fmaf(nv.z, nsc, xv.z * sc);
    o.w = fmaf(nv.w, nsc, xv.w * sc);

    __stcs(&out[idx], o);
}

extern "C" void kernel_launch(void* const* d_in, const int* in_sizes, int n_in,
                              void* d_out, int out_size)
{
    const float4* x      = (const float4*)d_in[0];
    const float4* noise  = (const float4*)d_in[1];
    const float*  scale  = (const float*)d_in[2];
    const int*    shifts = (const int*)d_in[3];
    float4* out = (float4*)d_out;

    const unsigned total = B_DIM * T_DIM * C4;   // 8,388,608
    const unsigned blocks = total / THREADS;     // 32768

    ts_augment_kernel<<<blocks, THREADS>>>(x, noise, scale, shifts, out);
}